// round 5
// baseline (speedup 1.0000x reference)
#include <cuda_runtime.h>

#define N_VOX    100000
#define CIN      64
#define COUT     64
#define NK       27
#define TILE_M   128
#define NTHREADS 128
#define LN_EPS   1e-5f
#define CENTER_K 13
#define CAP      416     // work-list capacity (mean ~160/block for 4.8% density)

// Static shared layout (floats):
//   regX : 8704  — accS[128][68] / As(64x128 dense) / Ys[128][68]
//   As2  : 1088  — 16 gathered rows, stride 68
//   listVK / listIdx : CAP ints each
//   cnt  : 1 int
#define REGX_OFF 0
#define A2_OFF   8704
#define LVK_OFF  9792
#define LIX_OFF  (9792 + CAP)
#define CNT_OFF  (9792 + 2*CAP)
#define SMEM_FLOATS (9792 + 2*CAP + 4)

__global__ __launch_bounds__(NTHREADS, 5)
void spconv_lin_ln_kernel(const float* __restrict__ feats,
                          const int*   __restrict__ nb,
                          const float* __restrict__ Wc,
                          const float* __restrict__ bc,
                          const float* __restrict__ Wl,
                          const float* __restrict__ bl,
                          const float* __restrict__ gamma,
                          const float* __restrict__ beta,
                          float* __restrict__ out)
{
    __shared__ float SM[SMEM_FLOATS];
    float* regX   = SM + REGX_OFF;
    float* As2    = SM + A2_OFF;
    int*   listVK = (int*)(SM + LVK_OFF);
    int*   listIdx= (int*)(SM + LIX_OFF);
    int*   cntP   = (int*)(SM + CNT_OFF);

    const int tid = threadIdx.x;
    const int block_row = blockIdx.x * TILE_M;
    const int gvox = block_row + tid;
    const bool active = (gvox < N_VOX);
    const int* nrow = nb + (long)gvox * NK;

    // ===== Phase 1: zero accS + cnt =====
    for (int t = tid; t < TILE_M * 68; t += NTHREADS) regX[t] = 0.0f;
    if (tid == 0) *cntP = 0;
    __syncthreads();

    // ===== Phase 2a: build compacted (voxel,tap,idx) list — no block syncs =====
    unsigned ovf = 0;
    {
        const unsigned lmask_lt = (1u << (tid & 31)) - 1u;
        #pragma unroll 1
        for (int kk = 0; kk < 26; kk++) {
            const int k = kk + (kk >= CENTER_K ? 1 : 0);
            const int idx = active ? nrow[k] : -1;
            const bool valid = (idx >= 0);
            unsigned bal = __ballot_sync(0xffffffffu, valid);
            if (bal) {
                int base = 0;
                if ((tid & 31) == 0) base = atomicAdd(cntP, __popc(bal));
                base = __shfl_sync(0xffffffffu, base, 0);
                if (valid) {
                    int pos = base + __popc(bal & lmask_lt);
                    if (pos < CAP) { listVK[pos] = (tid << 5) | k; listIdx[pos] = idx; }
                    else            ovf |= (1u << kk);
                }
            }
        }
    }
    __syncthreads();
    int total = *cntP;
    if (total > CAP) total = CAP;

    // ===== Phase 2b: passes of 16 rows; W read straight from gmem (L1-hot) =====
    for (int base = 0; base < total; base += 16) {
        const int rem = (total - base < 16) ? (total - base) : 16;
        // gather up to 16 feature rows into As2
        #pragma unroll
        for (int it = 0; it < 2; it++) {
            int s = tid + it * NTHREADS;
            int e = s >> 4, c4 = s & 15;
            if (e < rem) {
                float4 f = *((const float4*)(feats + (long)listIdx[base + e] * CIN) + c4);
                *(float4*)(As2 + e * 68 + 4 * c4) = f;
            }
        }
        __syncthreads();

        const int e = tid >> 3, j = tid & 7;
        const int vk = listVK[base + (e < rem ? e : 0)];
        const float* Wk = Wc + (long)(vk & 31) * (CIN * COUT);
        const float* A  = As2 + e * 68;
        float a8[8] = {0.f,0.f,0.f,0.f,0.f,0.f,0.f,0.f};
        #pragma unroll
        for (int c4 = 0; c4 < 16; c4++) {
            float4 av = *(const float4*)(A + 4 * c4);
            float aa[4] = {av.x, av.y, av.z, av.w};
            #pragma unroll
            for (int u = 0; u < 4; u++) {
                const float* Brow = Wk + (4 * c4 + u) * COUT + j * 8;
                float4 b0 = *(const float4*)Brow;
                float4 b1 = *(const float4*)(Brow + 4);
                a8[0] += aa[u] * b0.x;
                a8[1] += aa[u] * b0.y;
                a8[2] += aa[u] * b0.z;
                a8[3] += aa[u] * b0.w;
                a8[4] += aa[u] * b1.x;
                a8[5] += aa[u] * b1.y;
                a8[6] += aa[u] * b1.z;
                a8[7] += aa[u] * b1.w;
            }
        }
        if (e < rem) {
            float* P = regX + (vk >> 5) * 68 + j * 8;
            // same voxel may appear twice in one pass (different taps) -> shared atomics
            atomicAdd(P + 0, a8[0]);
            atomicAdd(P + 1, a8[1]);
            atomicAdd(P + 2, a8[2]);
            atomicAdd(P + 3, a8[3]);
            atomicAdd(P + 4, a8[4]);
            atomicAdd(P + 5, a8[5]);
            atomicAdd(P + 6, a8[6]);
            atomicAdd(P + 7, a8[7]);
        }
        __syncthreads();
    }

    // ===== Phase 2c: overflow fallback (statistically never taken) =====
    if (ovf) {
        #pragma unroll 1
        for (int kk = 0; kk < 26; kk++) if (ovf & (1u << kk)) {
            const int k = kk + (kk >= CENTER_K ? 1 : 0);
            const float* f  = feats + (long)nrow[k] * CIN;
            const float* Wk = Wc + (long)k * (CIN * COUT);
            float* P = regX + tid * 68;
            #pragma unroll 1
            for (int c = 0; c < CIN; c++) {
                float fc = f[c];
                #pragma unroll 1
                for (int o = 0; o < COUT; o++) P[o] += fc * Wk[c * COUT + o];
            }
        }
    }
    __syncthreads();

    // ===== Phase 3: merge accS + conv bias into registers =====
    const int i  = tid >> 3;
    const int j2 = tid & 7;
    const int r0 = i * 8;
    const int c0 = j2 * 8;

    float acc[8][8];
    {
        float bcv[8];
        #pragma unroll
        for (int oi = 0; oi < 8; oi++) bcv[oi] = bc[c0 + oi];
        #pragma unroll
        for (int vi = 0; vi < 8; vi++) {
            float4 s0 = *(const float4*)(regX + (r0 + vi) * 68 + c0);
            float4 s1 = *(const float4*)(regX + (r0 + vi) * 68 + c0 + 4);
            acc[vi][0] = s0.x + bcv[0];  acc[vi][1] = s0.y + bcv[1];
            acc[vi][2] = s0.z + bcv[2];  acc[vi][3] = s0.w + bcv[3];
            acc[vi][4] = s1.x + bcv[4];  acc[vi][5] = s1.y + bcv[5];
            acc[vi][6] = s1.z + bcv[6];  acc[vi][7] = s1.w + bcv[7];
        }
    }
    __syncthreads();           // accS consumed; regX becomes dense As

    // ===== Phase 4: center tap, dense (B via LDG, L1-hot) =====
    float* As = regX;          // 64 x 128
    {
        int idx = active ? nrow[CENTER_K] : -1;
        if (idx >= 0) {
            const float4* F4 = (const float4*)(feats + (long)idx * CIN);
            #pragma unroll
            for (int c4 = 0; c4 < 16; c4++) {
                float4 f = F4[c4];
                As[(4 * c4 + 0) * TILE_M + tid] = f.x;
                As[(4 * c4 + 1) * TILE_M + tid] = f.y;
                As[(4 * c4 + 2) * TILE_M + tid] = f.z;
                As[(4 * c4 + 3) * TILE_M + tid] = f.w;
            }
        } else {
            #pragma unroll
            for (int c4 = 0; c4 < 16; c4++) {
                As[(4 * c4 + 0) * TILE_M + tid] = 0.0f;
                As[(4 * c4 + 1) * TILE_M + tid] = 0.0f;
                As[(4 * c4 + 2) * TILE_M + tid] = 0.0f;
                As[(4 * c4 + 3) * TILE_M + tid] = 0.0f;
            }
        }
    }
    __syncthreads();

    {
        const float* Wk = Wc + (long)CENTER_K * (CIN * COUT);
        #pragma unroll 8
        for (int c = 0; c < CIN; c++) {
            float4 a0 = *(const float4*)(As + c * TILE_M + r0);
            float4 a1 = *(const float4*)(As + c * TILE_M + r0 + 4);
            float4 b0 = *(const float4*)(Wk + c * COUT + c0);
            float4 b1 = *(const float4*)(Wk + c * COUT + c0 + 4);
            float av[8] = {a0.x, a0.y, a0.z, a0.w, a1.x, a1.y, a1.z, a1.w};
            float bv[8] = {b0.x, b0.y, b0.z, b0.w, b1.x, b1.y, b1.z, b1.w};
            #pragma unroll
            for (int vi = 0; vi < 8; vi++)
                #pragma unroll
                for (int oi = 0; oi < 8; oi++)
                    acc[vi][oi] += av[vi] * bv[oi];
        }
    }
    __syncthreads();

    // ===== Phase 5: fused linear (B via LDG) =====
    #pragma unroll
    for (int oi = 0; oi < 8; oi++)
        #pragma unroll
        for (int vi = 0; vi < 8; vi++)
            As[(c0 + oi) * TILE_M + (r0 + vi)] = acc[vi][oi];
    __syncthreads();

    float acc2[8][8];
    #pragma unroll
    for (int a = 0; a < 8; a++)
        #pragma unroll
        for (int b = 0; b < 8; b++) acc2[a][b] = 0.0f;

    #pragma unroll 8
    for (int c = 0; c < COUT; c++) {
        float4 a0 = *(const float4*)(As + c * TILE_M + r0);
        float4 a1 = *(const float4*)(As + c * TILE_M + r0 + 4);
        float4 b0 = *(const float4*)(Wl + c * COUT + c0);
        float4 b1 = *(const float4*)(Wl + c * COUT + c0 + 4);
        float av[8] = {a0.x, a0.y, a0.z, a0.w, a1.x, a1.y, a1.z, a1.w};
        float bv[8] = {b0.x, b0.y, b0.z, b0.w, b1.x, b1.y, b1.z, b1.w};
        #pragma unroll
        for (int vi = 0; vi < 8; vi++)
            #pragma unroll
            for (int oi = 0; oi < 8; oi++)
                acc2[vi][oi] += av[vi] * bv[oi];
    }
    __syncthreads();           // done with As; regX becomes Ys

    {
        float blv[8];
        #pragma unroll
        for (int oi = 0; oi < 8; oi++) blv[oi] = bl[c0 + oi];
        #pragma unroll
        for (int vi = 0; vi < 8; vi++)
            #pragma unroll
            for (int oi = 0; oi < 8; oi++)
                regX[(r0 + vi) * 68 + (c0 + oi)] = acc2[vi][oi] + blv[oi];
    }
    __syncthreads();

    // ===== Phase 6: layernorm =====
    if (active) {
        const float* y = regX + tid * 68;
        float s = 0.0f;
        #pragma unroll
        for (int c4 = 0; c4 < 16; c4++) {
            float4 f = *(const float4*)(y + 4 * c4);
            s += f.x + f.y + f.z + f.w;
        }
        float mu = s * (1.0f / 64.0f);
        float v2 = 0.0f;
        #pragma unroll
        for (int c4 = 0; c4 < 16; c4++) {
            float4 f = *(const float4*)(y + 4 * c4);
            float dx = f.x - mu, dy = f.y - mu, dz = f.z - mu, dw = f.w - mu;
            v2 += dx * dx + dy * dy + dz * dz + dw * dw;
        }
        float rstd = rsqrtf(v2 * (1.0f / 64.0f) + LN_EPS);
        float4* o4 = (float4*)(out + (long)gvox * COUT);
        #pragma unroll
        for (int c4 = 0; c4 < 16; c4++) {
            float4 f = *(const float4*)(y + 4 * c4);
            float4 g = *(const float4*)(gamma + 4 * c4);
            float4 b = *(const float4*)(beta + 4 * c4);
            float4 r;
            r.x = g.x * (f.x - mu) * rstd + b.x;
            r.y = g.y * (f.y - mu) * rstd + b.y;
            r.z = g.z * (f.z - mu) * rstd + b.z;
            r.w = g.w * (f.w - mu) * rstd + b.w;
            o4[c4] = r;
        }
    }
}

extern "C" void kernel_launch(void* const* d_in, const int* in_sizes, int n_in,
                              void* d_out, int out_size)
{
    const float* feats = (const float*)d_in[0];
    const int*   nb    = (const int*)d_in[1];
    const float* Wc    = (const float*)d_in[2];
    const float* bc    = (const float*)d_in[3];
    const float* Wl    = (const float*)d_in[4];
    const float* bl    = (const float*)d_in[5];
    const float* gamma = (const float*)d_in[6];
    const float* beta  = (const float*)d_in[7];
    float* out = (float*)d_out;

    int grid = (N_VOX + TILE_M - 1) / TILE_M;   // 782
    spconv_lin_ln_kernel<<<grid, NTHREADS>>>(feats, nb, Wc, bc, Wl, bl, gamma, beta, out);
}

// round 7
// speedup vs baseline: 2.9000x; 2.9000x over previous
#include <cuda_runtime.h>
#include <cuda_fp16.h>
#include <cstdint>

#define N_VOX    100000
#define NK       27
#define LN_EPS   1e-5f
#define NTHREADS 128
#define GRID_M   ((N_VOX + 127) / 128)   // 782

// smem stage: A 128x(64+8 pad) fp16 = 18432B ; W 64x(64+8) fp16 = 9216B
#define ROWB    144                      // row stride bytes (72 fp16)
#define A_BYTES 18432
#define STAGE   27648
#define SMEM_BYTES (2 * STAGE)           // 55296

// Precomputed fp16 data (static device globals, no allocation)
__device__ __align__(16) __half g_f16[N_VOX * 64];
__device__ __align__(16) __half g_w16[28 * 4096];   // [tap][cout][cin], tap27 = W_lin

// ---------- helpers ----------
__device__ __forceinline__ uint32_t smem_u32(const void* p) {
    uint32_t a;
    asm("{ .reg .u64 t; cvta.to.shared.u64 t, %1; cvt.u32.u64 %0, t; }" : "=r"(a) : "l"(p));
    return a;
}
__device__ __forceinline__ uint32_t lds32(uint32_t a) {
    uint32_t v;
    asm volatile("ld.shared.b32 %0, [%1];" : "=r"(v) : "r"(a));
    return v;
}
__device__ __forceinline__ void sts32(uint32_t a, uint32_t v) {
    asm volatile("st.shared.b32 [%0], %1;" :: "r"(a), "r"(v));
}
__device__ __forceinline__ void cpa16(uint32_t dst, const void* src) {
    asm volatile("cp.async.cg.shared.global [%0], [%1], 16;" :: "r"(dst), "l"(src));
}
#define CP_COMMIT()  asm volatile("cp.async.commit_group;" ::: "memory")
#define CP_WAIT(n)   asm volatile("cp.async.wait_group %0;" :: "n"(n) : "memory")

__device__ __forceinline__ void mma16816(float* c, const uint32_t* a,
                                         uint32_t b0, uint32_t b1) {
    asm volatile(
        "mma.sync.aligned.m16n8k16.row.col.f32.f16.f16.f32 "
        "{%0,%1,%2,%3}, {%4,%5,%6,%7}, {%8,%9}, {%0,%1,%2,%3};"
        : "+f"(c[0]), "+f"(c[1]), "+f"(c[2]), "+f"(c[3])
        : "r"(a[0]), "r"(a[1]), "r"(a[2]), "r"(a[3]), "r"(b0), "r"(b1));
}

// ---------- pre-kernels ----------
__global__ void prep_feats(const float* __restrict__ feats) {
    int t = blockIdx.x * blockDim.x + threadIdx.x;       // 8 floats per thread
    if (t >= N_VOX * 8) return;
    const float4* F = (const float4*)feats;
    float4 f0 = F[t * 2], f1 = F[t * 2 + 1];
    __half2 h0 = __floats2half2_rn(f0.x, f0.y);
    __half2 h1 = __floats2half2_rn(f0.z, f0.w);
    __half2 h2 = __floats2half2_rn(f1.x, f1.y);
    __half2 h3 = __floats2half2_rn(f1.z, f1.w);
    uint4 o;
    o.x = *(uint32_t*)&h0; o.y = *(uint32_t*)&h1;
    o.z = *(uint32_t*)&h2; o.w = *(uint32_t*)&h3;
    ((uint4*)g_f16)[t] = o;
}
__global__ void prep_w(const float* __restrict__ Wc, const float* __restrict__ Wl) {
    int e = blockIdx.x * blockDim.x + threadIdx.x;       // (tap, o, c)
    if (e >= 28 * 4096) return;
    int k = e >> 12, rem = e & 4095;
    int o = rem >> 6, c = rem & 63;
    float w = (k < 27) ? Wc[k * 4096 + c * 64 + o] : Wl[c * 64 + o];
    g_w16[e] = __float2half_rn(w);
}

// ---------- main ----------
__global__ __launch_bounds__(NTHREADS, 4)
void conv_mma_kernel(const int* __restrict__ nb, const float* __restrict__ bc,
                     const float* __restrict__ bl, const float* __restrict__ gamma,
                     const float* __restrict__ beta, float* __restrict__ out)
{
    extern __shared__ __align__(16) char smem[];
    const uint32_t sb = smem_u32(smem);
    const int tid  = threadIdx.x;
    const int lane = tid & 31;
    const int w    = tid >> 5;
    const int group = lane >> 2;     // 0..7
    const int qp    = lane & 3;      // 0..3
    const int gvox = blockIdx.x * NTHREADS + tid;
    const bool active = gvox < N_VOX;
    const int* nrow = nb + (long)gvox * NK;

    float c[2][8][4];
    #pragma unroll
    for (int mi = 0; mi < 2; mi++)
        #pragma unroll
        for (int nt = 0; nt < 8; nt++)
            #pragma unroll
            for (int r = 0; r < 4; r++) c[mi][nt][r] = 0.0f;

    // ---- issue helpers ----
    auto issueA = [&](int s, int k) {
        uint32_t dst = sb + s * STAGE + tid * ROWB;
        int idx = active ? nrow[k] : -1;
        if (idx >= 0) {
            const char* src = (const char*)(g_f16 + (size_t)idx * 64);
            #pragma unroll
            for (int j = 0; j < 8; j++) cpa16(dst + j * 16, src + j * 16);
        } else {
            float4 z = make_float4(0.f, 0.f, 0.f, 0.f);
            #pragma unroll
            for (int j = 0; j < 8; j++)
                *(float4*)(smem + s * STAGE + tid * ROWB + j * 16) = z;
        }
    };
    auto issueW = [&](uint32_t wbase, int k) {
        const char* srcb = (const char*)(g_w16 + (size_t)k * 4096);
        #pragma unroll
        for (int t = 0; t < 4; t++) {
            int ch = tid + t * 128;          // 512 chunks of 16B
            int row = ch >> 3, j = ch & 7;
            cpa16(wbase + row * ROWB + j * 16, srcb + ch * 16);
        }
    };
    auto do_tap = [&](uint32_t Ab, uint32_t Wb) {
        #pragma unroll
        for (int k4 = 0; k4 < 4; k4++) {
            const int k0 = k4 * 16;
            uint32_t a[2][4];
            #pragma unroll
            for (int mi = 0; mi < 2; mi++) {
                uint32_t base = Ab + (w * 32 + mi * 16 + group) * ROWB + (k0 + qp * 2) * 2;
                a[mi][0] = lds32(base);
                a[mi][1] = lds32(base + 8 * ROWB);
                a[mi][2] = lds32(base + 16);
                a[mi][3] = lds32(base + 8 * ROWB + 16);
            }
            #pragma unroll
            for (int nt = 0; nt < 8; nt++) {
                uint32_t baddr = Wb + (nt * 8 + group) * ROWB + (k0 + qp * 2) * 2;
                uint32_t b0 = lds32(baddr);
                uint32_t b1 = lds32(baddr + 16);
                mma16816(c[0][nt], a[0], b0, b1);
                mma16816(c[1][nt], a[1], b0, b1);
            }
        }
    };

    // ---- prologue: taps 0,1 ----
    issueA(0, 0); issueW(sb + 0 * STAGE + A_BYTES, 0); CP_COMMIT();
    issueA(1, 1); issueW(sb + 1 * STAGE + A_BYTES, 1); CP_COMMIT();

    // ---- conv mainloop ----
    #pragma unroll 1
    for (int k = 0; k < NK; k++) {
        const int s = k & 1;
        if (k < NK - 1) CP_WAIT(1); else CP_WAIT(0);
        __syncthreads();
        do_tap(sb + s * STAGE, sb + s * STAGE + A_BYTES);
        __syncthreads();
        if (k + 2 < NK) {
            issueA(s, k + 2);
            issueW(sb + s * STAGE + A_BYTES, k + 2);
            CP_COMMIT();
        }
    }

    // ---- epilogue: +bc, convert to fp16 X in stage0 A; load W_lin ----
    issueW(sb + A_BYTES, 27); CP_COMMIT();
    #pragma unroll
    for (int nt = 0; nt < 8; nt++) {
        const int col0 = nt * 8 + qp * 2;
        const float b0 = bc[col0], b1 = bc[col0 + 1];
        #pragma unroll
        for (int mi = 0; mi < 2; mi++) {
            float x0 = c[mi][nt][0] + b0;
            float x1 = c[mi][nt][1] + b1;
            float x2 = c[mi][nt][2] + b0;
            float x3 = c[mi][nt][3] + b1;
            __half2 p0 = __floats2half2_rn(x0, x1);
            __half2 p1 = __floats2half2_rn(x2, x3);
            const int r0 = w * 32 + mi * 16 + group;
            sts32(sb + r0 * ROWB + col0 * 2, *(uint32_t*)&p0);
            sts32(sb + (r0 + 8) * ROWB + col0 * 2, *(uint32_t*)&p1);
        }
    }
    CP_WAIT(0);
    __syncthreads();

    // ---- linear GEMM (tap 27) ----
    #pragma unroll
    for (int mi = 0; mi < 2; mi++)
        #pragma unroll
        for (int nt = 0; nt < 8; nt++)
            #pragma unroll
            for (int r = 0; r < 4; r++) c[mi][nt][r] = 0.0f;
    do_tap(sb, sb + A_BYTES);

    // ---- +bl, layernorm in registers ----
    float sum[2][2] = {{0.f, 0.f}, {0.f, 0.f}};
    float sq [2][2] = {{0.f, 0.f}, {0.f, 0.f}};
    #pragma unroll
    for (int nt = 0; nt < 8; nt++) {
        const int col0 = nt * 8 + qp * 2;
        const float b0 = bl[col0], b1 = bl[col0 + 1];
        #pragma unroll
        for (int mi = 0; mi < 2; mi++) {
            float y0 = c[mi][nt][0] + b0, y1 = c[mi][nt][1] + b1;
            float y2 = c[mi][nt][2] + b0, y3 = c[mi][nt][3] + b1;
            c[mi][nt][0] = y0; c[mi][nt][1] = y1;
            c[mi][nt][2] = y2; c[mi][nt][3] = y3;
            sum[mi][0] += y0 + y1;            sq[mi][0] += y0 * y0 + y1 * y1;
            sum[mi][1] += y2 + y3;            sq[mi][1] += y2 * y2 + y3 * y3;
        }
    }
    #pragma unroll
    for (int off = 1; off <= 2; off <<= 1) {
        #pragma unroll
        for (int mi = 0; mi < 2; mi++)
            #pragma unroll
            for (int h = 0; h < 2; h++) {
                sum[mi][h] += __shfl_xor_sync(0xffffffffu, sum[mi][h], off);
                sq [mi][h] += __shfl_xor_sync(0xffffffffu, sq [mi][h], off);
            }
    }
    float mu[2][2], rs[2][2];
    #pragma unroll
    for (int mi = 0; mi < 2; mi++)
        #pragma unroll
        for (int h = 0; h < 2; h++) {
            float m = sum[mi][h] * (1.0f / 64.0f);
            float v = sq[mi][h] * (1.0f / 64.0f) - m * m;
            mu[mi][h] = m;
            rs[mi][h] = rsqrtf(v + LN_EPS);
        }
    const int base_row = blockIdx.x * NTHREADS + w * 32 + group;
    #pragma unroll
    for (int nt = 0; nt < 8; nt++) {
        const int col0 = nt * 8 + qp * 2;
        const float g0 = gamma[col0], g1 = gamma[col0 + 1];
        const float be0 = beta[col0], be1 = beta[col0 + 1];
        #pragma unroll
        for (int mi = 0; mi < 2; mi++) {
            int r0 = base_row + mi * 16;
            int r1 = r0 + 8;
            if (r0 < N_VOX) {
                float2 o;
                o.x = g0 * (c[mi][nt][0] - mu[mi][0]) * rs[mi][0] + be0;
                o.y = g1 * (c[mi][nt][1] - mu[mi][0]) * rs[mi][0] + be1;
                *(float2*)(out + (size_t)r0 * 64 + col0) = o;
            }
            if (r1 < N_VOX) {
                float2 o;
                o.x = g0 * (c[mi][nt][2] - mu[mi][1]) * rs[mi][1] + be0;
                o.y = g1 * (c[mi][nt][3] - mu[mi][1]) * rs[mi][1] + be1;
                *(float2*)(out + (size_t)r1 * 64 + col0) = o;
            }
        }
    }
}

// ---------- launch ----------
extern "C" void kernel_launch(void* const* d_in, const int* in_sizes, int n_in,
                              void* d_out, int out_size)
{
    const float* feats = (const float*)d_in[0];
    const int*   nb    = (const int*)d_in[1];
    const float* Wc    = (const float*)d_in[2];
    const float* bc    = (const float*)d_in[3];
    const float* Wl    = (const float*)d_in[4];
    const float* bl    = (const float*)d_in[5];
    const float* gamma = (const float*)d_in[6];
    const float* beta  = (const float*)d_in[7];
    float* out = (float*)d_out;

    static int init = 0;
    if (!init) {
        cudaFuncSetAttribute(conv_mma_kernel,
                             cudaFuncAttributeMaxDynamicSharedMemorySize, SMEM_BYTES);
        init = 1;
    }
    prep_feats<<<(N_VOX * 8 + 255) / 256, 256>>>(feats);
    prep_w<<<(28 * 4096 + 255) / 256, 256>>>(Wc, Wl);
    conv_mma_kernel<<<GRID_M, NTHREADS, SMEM_BYTES>>>(nb, bc, bl, gamma, beta, out);
}